// round 1
// baseline (speedup 1.0000x reference)
#include <cuda_runtime.h>
#include <math.h>

#define Bsz 4
#define SEQ 4096
#define WID 768
#define NH  12
#define HDm 64
#define MBm 16
#define NBt 256           // SEQ / MBm
#define EPSV 1e-6f

// ------------------------- scratch (device globals) -------------------------
__device__ float g_xqk [Bsz*SEQ*WID];
__device__ float g_xv  [Bsz*SEQ*WID];
__device__ float g_gate[Bsz*SEQ*WID];   // gelu-arg, then overwritten with gate*z
__device__ float g_xq  [Bsz*SEQ*WID];
__device__ float g_xk  [Bsz*SEQ*WID];
__device__ float g_ttt [Bsz*SEQ*WID];
__device__ float g_lr  [Bsz*NH*SEQ];

// ------------------------- helpers -------------------------
__device__ __forceinline__ float wred(float v) {
#pragma unroll
    for (int o = 16; o; o >>= 1) v += __shfl_xor_sync(0xffffffffu, v, o);
    return v;
}

__device__ __forceinline__ unsigned long long bcast2(float x) {
    unsigned long long u = (unsigned long long)__float_as_uint(x);
    return u | (u << 32);
}
__device__ __forceinline__ void fma2(unsigned long long& acc,
                                     unsigned long long a, unsigned long long b) {
    asm("fma.rn.f32x2 %0, %1, %2, %0;" : "+l"(acc) : "l"(a), "l"(b));
}
__device__ __forceinline__ float2 up2(unsigned long long v) {
    return make_float2(__uint_as_float((unsigned)v), __uint_as_float((unsigned)(v >> 32)));
}

// ------------------------- SGEMM: C[M,N] = A[M,K] @ B[K,N], fp32, f32x2 FMA --
// BM=128 BN=128 BK=16, 256 threads, 8x8 micro-tile. M%128==0, N%128==0, K%16==0.
__global__ __launch_bounds__(256) void sgemm_kernel(
    const float* __restrict__ A, const float* __restrict__ B, float* __restrict__ C,
    int M, int N, int K)
{
    __shared__ float As[16][132];   // transposed A tile, padded
    __shared__ float Bs[16][128];

    const int tid = threadIdx.x;
    const int bm = blockIdx.y * 128;
    const int bn = blockIdx.x * 128;
    const int tx = tid & 15, ty = tid >> 4;

    unsigned long long acc[8][4];
#pragma unroll
    for (int i = 0; i < 8; i++)
#pragma unroll
        for (int j = 0; j < 4; j++) acc[i][j] = 0ULL;

    for (int k0 = 0; k0 < K; k0 += 16) {
#pragma unroll
        for (int l = 0; l < 2; l++) {
            int li = tid + l * 256;          // 0..511
            int row = li >> 2;               // 0..127
            int kc  = (li & 3) * 4;          // 0,4,8,12
            float4 v = *(const float4*)(A + (size_t)(bm + row) * K + k0 + kc);
            As[kc + 0][row] = v.x; As[kc + 1][row] = v.y;
            As[kc + 2][row] = v.z; As[kc + 3][row] = v.w;
        }
#pragma unroll
        for (int l = 0; l < 2; l++) {
            int li = tid + l * 256;
            int kr  = li >> 5;               // 0..15
            int col = (li & 31) * 4;
            *(float4*)(&Bs[kr][col]) = *(const float4*)(B + (size_t)(k0 + kr) * N + bn + col);
        }
        __syncthreads();

#pragma unroll
        for (int k = 0; k < 16; k++) {
            float4 a0 = *(const float4*)(&As[k][ty * 8]);
            float4 a1 = *(const float4*)(&As[k][ty * 8 + 4]);
            ulonglong2 b01 = *(const ulonglong2*)(&Bs[k][tx * 8]);
            ulonglong2 b23 = *(const ulonglong2*)(&Bs[k][tx * 8 + 4]);
            unsigned long long bp[4] = {b01.x, b01.y, b23.x, b23.y};
            float av[8] = {a0.x, a0.y, a0.z, a0.w, a1.x, a1.y, a1.z, a1.w};
#pragma unroll
            for (int i = 0; i < 8; i++) {
                unsigned long long ap = bcast2(av[i]);
#pragma unroll
                for (int j = 0; j < 4; j++) fma2(acc[i][j], ap, bp[j]);
            }
        }
        __syncthreads();
    }

#pragma unroll
    for (int i = 0; i < 8; i++) {
        float* crow = C + (size_t)(bm + ty * 8 + i) * N + bn + tx * 8;
        float2 p0 = up2(acc[i][0]), p1 = up2(acc[i][1]);
        float2 p2 = up2(acc[i][2]), p3 = up2(acc[i][3]);
        *(float4*)(crow)     = make_float4(p0.x, p0.y, p1.x, p1.y);
        *(float4*)(crow + 4) = make_float4(p2.x, p2.y, p3.x, p3.y);
    }
}

// ------------------------- lr logits: sigmoid(hidden . lrk[h] + lrb[h]) / 64 --
__global__ __launch_bounds__(256) void lr_kernel(
    const float* __restrict__ hidden, const float* __restrict__ lrk,
    const float* __restrict__ lrb)
{
    __shared__ float sk[NH * WID];
    const int tid = threadIdx.x;
    for (int i = tid; i < NH * WID; i += 256) sk[i] = lrk[i];
    __syncthreads();

    const int gw = blockIdx.x * 8 + (tid >> 5);   // row index b*SEQ+n, grid exact
    const int lane = tid & 31;
    const float* hrow = hidden + (size_t)gw * WID;

    float acc[NH];
#pragma unroll
    for (int h = 0; h < NH; h++) acc[h] = 0.f;
    for (int w = lane; w < WID; w += 32) {
        float hv = hrow[w];
#pragma unroll
        for (int h = 0; h < NH; h++) acc[h] += hv * sk[h * WID + w];
    }
    const int b = gw >> 12, n = gw & (SEQ - 1);
#pragma unroll
    for (int h = 0; h < NH; h++) {
        float v = wred(acc[h]);
        if (lane == 0) {
            float x = v + lrb[h];
            g_lr[(size_t)(b * NH + h) * SEQ + n] = (1.f / (1.f + expf(-x))) * (1.f / 64.f);
        }
    }
}

// ------------------------- causal depthwise conv (W=4) + RoPE ---------------
__global__ __launch_bounds__(256) void conv_rope_kernel(
    const float* __restrict__ cqk, const float* __restrict__ cqb,
    const float* __restrict__ ckk, const float* __restrict__ ckb)
{
    int idx = blockIdx.x * blockDim.x + threadIdx.x;
    const int total = Bsz * SEQ * 384;
    if (idx >= total) return;
    int p = idx % 384;
    int n = (idx / 384) % SEQ;
    int b = idx / (384 * SEQ);
    int h = p >> 5;
    int j = p & 31;
    int ce = h * 64 + 2 * j;

    const float* xbase = g_xqk + (size_t)b * SEQ * WID + ce;
    float qe = cqb[ce], qo = cqb[ce + 1];
    float ke = ckb[ce], ko = ckb[ce + 1];
#pragma unroll
    for (int t = 0; t < 4; t++) {
        int nn = n - 3 + t;
        if (nn >= 0) {
            float2 x  = *(const float2*)(xbase + (size_t)nn * WID);
            float2 kq = *(const float2*)(cqk + t * WID + ce);
            float2 kk = *(const float2*)(ckk + t * WID + ce);
            qe += x.x * kq.x; qo += x.y * kq.y;
            ke += x.x * kk.x; ko += x.y * kk.y;
        }
    }
    int pos = n & 15;
    float freq = expf(-9.210340371976184f * (float)j * (1.f / 32.f)); // 1/10000^(2j/64)
    float ang = (float)pos * freq;
    float c = cosf(ang), s = sinf(ang);
    size_t o = ((size_t)b * SEQ + n) * WID + ce;
    *(float2*)(g_xq + o) = make_float2(qe * c - qo * s, qe * s + qo * c);
    *(float2*)(g_xk + o) = make_float2(ke * c - ko * s, ke * s + ko * c);
}

// ------------------------- TTT scan: one CTA per (b,h) chain -----------------
__global__ __launch_bounds__(256) void ttt_scan_kernel(
    const float* __restrict__ W1in, const float* __restrict__ b1in,
    const float* __restrict__ gin,  const float* __restrict__ bbin,
    const float* __restrict__ lti)
{
    __shared__ float W1s[64 * 64];
    __shared__ float b1s[64], gvs[64], bvs[64];
    __shared__ float sXQ[16 * 68], sXK[16 * 68], sTT[16 * 68], sZ[16 * 68], sG[16 * 68];
    __shared__ float Cf[16 * 16];
    __shared__ float lr[16], toki[16], mu[16], rstd[16], s1[16], s2[16];

    const int tid = threadIdx.x;
    const int bh = blockIdx.x;
    const int b = bh / NH, h = bh % NH;

    for (int i = tid; i < 4096; i += 256) W1s[i] = W1in[h * 4096 + i];
    if (tid < 64) {
        b1s[tid] = b1in[h * 64 + tid];
        gvs[tid] = gin[h * 64 + tid];
        bvs[tid] = bbin[h * 64 + tid];
    }
    if (tid < 16) toki[tid] = fmaxf(1.f / (float)(tid + 1) + lti[tid], 0.f);

    const int r = tid >> 4;            // row 0..15
    const int c0 = (tid & 15) * 4;     // col group
    const int lane = tid & 31, wid = tid >> 5;
    const size_t gbase = (size_t)b * SEQ * WID + h * 64;
    const float* lrp = g_lr + (size_t)bh * SEQ;

    __syncthreads();

    for (int nb = 0; nb < NBt; nb++) {
        const size_t off = gbase + (size_t)(nb * MBm + r) * WID + c0;
        float4 q4 = *(const float4*)(g_xq + off);
        float4 k4 = *(const float4*)(g_xk + off);
        float4 v4 = *(const float4*)(g_xv + off);
        __syncthreads();  // previous iteration's readers of sXQ/sZ done
        *(float4*)(sXQ + r * 68 + c0) = q4;
        *(float4*)(sXK + r * 68 + c0) = k4;
        *(float4*)(sTT + r * 68 + c0) = make_float4(v4.x - k4.x, v4.y - k4.y,
                                                    v4.z - k4.z, v4.w - k4.w);
        if (tid < 16) lr[tid] = lrp[nb * MBm + tid];
        __syncthreads();

        // coef[i][m] = eta[i][m]*(Attn[i][m]+1) for m<=i  (merges tril(eta)@g and (eta*Attn)@g)
        {
            const int i = r, m = tid & 15;
            float cf = 0.f;
            if (m <= i) {
                float d = 0.f;
#pragma unroll 8
                for (int k = 0; k < 64; k++) d += sXQ[i * 68 + k] * sXK[m * 68 + k];
                cf = toki[i] * lr[m] * (d + 1.f);
            }
            Cf[i * 16 + m] = cf;
        }
        // Z1 = XK @ W1 + b1
        {
            float4 acc = make_float4(b1s[c0], b1s[c0 + 1], b1s[c0 + 2], b1s[c0 + 3]);
#pragma unroll 8
            for (int k = 0; k < 64; k++) {
                float xk = sXK[r * 68 + k];
                float4 w = *(const float4*)(W1s + k * 64 + c0);
                acc.x = fmaf(xk, w.x, acc.x); acc.y = fmaf(xk, w.y, acc.y);
                acc.z = fmaf(xk, w.z, acc.z); acc.w = fmaf(xk, w.w, acc.w);
            }
            *(float4*)(sZ + r * 68 + c0) = acc;
        }
        __syncthreads();

        // row stats of Z1
        for (int rr = wid; rr < 16; rr += 8) {
            float x0 = sZ[rr * 68 + lane], x1 = sZ[rr * 68 + lane + 32];
            float s = wred(x0 + x1);
            float q = wred(x0 * x0 + x1 * x1);
            if (lane == 0) {
                float m = s * (1.f / 64.f);
                mu[rr] = m;
                rstd[rr] = rsqrtf(q * (1.f / 64.f) - m * m + EPSV);
            }
        }
        __syncthreads();

        // gxh = (g*x_hat + b - target) * g
        {
            float m = mu[r], rs = rstd[r];
            float4 z = *(const float4*)(sZ + r * 68 + c0);
            float4 t = *(const float4*)(sTT + r * 68 + c0);
            float g0 = gvs[c0], g1 = gvs[c0 + 1], g2 = gvs[c0 + 2], g3 = gvs[c0 + 3];
            float b0 = bvs[c0], b1v = bvs[c0 + 1], b2 = bvs[c0 + 2], b3 = bvs[c0 + 3];
            float4 gx;
            gx.x = (g0 * ((z.x - m) * rs) + b0 - t.x) * g0;
            gx.y = (g1 * ((z.y - m) * rs) + b1v - t.y) * g1;
            gx.z = (g2 * ((z.z - m) * rs) + b2 - t.z) * g2;
            gx.w = (g3 * ((z.w - m) * rs) + b3 - t.w) * g3;
            *(float4*)(sG + r * 68 + c0) = gx;
        }
        __syncthreads();

        // sum(gxh), sum(gxh * x_hat)
        for (int rr = wid; rr < 16; rr += 8) {
            float m = mu[rr], rs = rstd[rr];
            float a0 = sG[rr * 68 + lane], a1 = sG[rr * 68 + lane + 32];
            float xh0 = (sZ[rr * 68 + lane] - m) * rs;
            float xh1 = (sZ[rr * 68 + lane + 32] - m) * rs;
            float sa = wred(a0 + a1);
            float sb = wred(a0 * xh0 + a1 * xh1);
            if (lane == 0) { s1[rr] = sa; s2[rr] = sb; }
        }
        __syncthreads();

        // grad = (64*gxh - s1 - x_hat*s2) * rstd/64
        {
            float m = mu[r], rs = rstd[r], sa = s1[r], sb = s2[r], sc = rs * (1.f / 64.f);
            float4 z = *(const float4*)(sZ + r * 68 + c0);
            float4 gx = *(const float4*)(sG + r * 68 + c0);
            float4 gr;
            gr.x = (64.f * gx.x - sa - ((z.x - m) * rs) * sb) * sc;
            gr.y = (64.f * gx.y - sa - ((z.y - m) * rs) * sb) * sc;
            gr.z = (64.f * gx.z - sa - ((z.z - m) * rs) * sb) * sc;
            gr.w = (64.f * gx.w - sa - ((z.w - m) * rs) * sb) * sc;
            *(float4*)(sG + r * 68 + c0) = gr;
        }
        __syncthreads();

        // Z1_bar = XQ@W1 + b1 - coef@grad
        {
            float4 acc = make_float4(b1s[c0], b1s[c0 + 1], b1s[c0 + 2], b1s[c0 + 3]);
#pragma unroll 8
            for (int k = 0; k < 64; k++) {
                float xq = sXQ[r * 68 + k];
                float4 w = *(const float4*)(W1s + k * 64 + c0);
                acc.x = fmaf(xq, w.x, acc.x); acc.y = fmaf(xq, w.y, acc.y);
                acc.z = fmaf(xq, w.z, acc.z); acc.w = fmaf(xq, w.w, acc.w);
            }
#pragma unroll
            for (int m = 0; m < 16; m++) {
                float cf = Cf[r * 16 + m];
                float4 g = *(const float4*)(sG + m * 68 + c0);
                acc.x -= cf * g.x; acc.y -= cf * g.y;
                acc.z -= cf * g.z; acc.w -= cf * g.w;
            }
            *(float4*)(sZ + r * 68 + c0) = acc;
        }
        __syncthreads();

        // stats of Z1_bar  +  W1/b1 update (disjoint data, same phase)
        for (int rr = wid; rr < 16; rr += 8) {
            float x0 = sZ[rr * 68 + lane], x1 = sZ[rr * 68 + lane + 32];
            float s = wred(x0 + x1);
            float q = wred(x0 * x0 + x1 * x1);
            if (lane == 0) {
                float m = s * (1.f / 64.f);
                mu[rr] = m;
                rstd[rr] = rsqrtf(q * (1.f / 64.f) - m * m + EPSV);
            }
        }
        {
            const int d = tid & 63;
            const float let15 = toki[15];
            float gvv[16];
            float bs = 0.f;
#pragma unroll
            for (int m = 0; m < 16; m++) {
                gvv[m] = let15 * lr[m] * sG[m * 68 + d];
                bs += gvv[m];
            }
            const int kb = tid >> 6;
#pragma unroll
            for (int jj = 0; jj < 16; jj++) {
                int k = kb + 4 * jj;
                float s = 0.f;
#pragma unroll
                for (int m = 0; m < 16; m++) s += sXK[m * 68 + k] * gvv[m];
                W1s[k * 64 + d] -= s;
            }
            if (tid < 64) b1s[tid] -= bs;
        }
        __syncthreads();

        // out = XQ + ln_fwd(Z1_bar)
        {
            float m = mu[r], rs = rstd[r];
            float4 z = *(const float4*)(sZ + r * 68 + c0);
            float4 q = *(const float4*)(sXQ + r * 68 + c0);
            float4 o;
            o.x = q.x + gvs[c0 + 0] * ((z.x - m) * rs) + bvs[c0 + 0];
            o.y = q.y + gvs[c0 + 1] * ((z.y - m) * rs) + bvs[c0 + 1];
            o.z = q.z + gvs[c0 + 2] * ((z.z - m) * rs) + bvs[c0 + 2];
            o.w = q.w + gvs[c0 + 3] * ((z.w - m) * rs) + bvs[c0 + 3];
            *(float4*)(g_ttt + off) = o;
        }
    }
}

// ------------------------- post: t = gelu(gate) * LN(out) -------------------
__global__ __launch_bounds__(256) void postfuse_kernel(
    const float* __restrict__ pns, const float* __restrict__ pnb)
{
    __shared__ float ws[8], wq2[8];
    __shared__ float smu, srs;
    const int row = blockIdx.x;
    const int tid = threadIdx.x;
    const int lane = tid & 31, wid = tid >> 5;
    const float* o = g_ttt + (size_t)row * WID;
    float* gp = g_gate + (size_t)row * WID;

    float v[3], s = 0.f, q = 0.f;
#pragma unroll
    for (int i = 0; i < 3; i++) {
        v[i] = o[tid + i * 256];
        s += v[i]; q += v[i] * v[i];
    }
    s = wred(s); q = wred(q);
    if (lane == 0) { ws[wid] = s; wq2[wid] = q; }
    __syncthreads();
    if (tid == 0) {
        float S = 0.f, Q = 0.f;
#pragma unroll
        for (int i = 0; i < 8; i++) { S += ws[i]; Q += wq2[i]; }
        float m = S * (1.f / 768.f);
        smu = m;
        srs = rsqrtf(Q * (1.f / 768.f) - m * m + EPSV);
    }
    __syncthreads();
    const float m = smu, rs = srs;
#pragma unroll
    for (int i = 0; i < 3; i++) {
        int c = tid + i * 256;
        float z = pns[c] * ((v[i] - m) * rs) + pnb[c];
        float x = gp[c];
        float gl = 0.5f * x * (1.f + tanhf(0.7978845608028654f * (x + 0.044715f * x * x * x)));
        gp[c] = gl * z;
    }
}

// ------------------------- launch --------------------------------------------
extern "C" void kernel_launch(void* const* d_in, const int* in_sizes, int n_in,
                              void* d_out, int out_size)
{
    const float* hidden = (const float*)d_in[0];
    const float* wq  = (const float*)d_in[1];
    const float* wv  = (const float*)d_in[2];
    const float* wo  = (const float*)d_in[3];
    const float* wg  = (const float*)d_in[4];
    const float* cqk = (const float*)d_in[5];
    const float* cqb = (const float*)d_in[6];
    const float* ckk = (const float*)d_in[7];
    const float* ckb = (const float*)d_in[8];
    const float* W1  = (const float*)d_in[9];
    const float* b1  = (const float*)d_in[10];
    const float* tns = (const float*)d_in[11];
    const float* tnb = (const float*)d_in[12];
    const float* lrk = (const float*)d_in[13];
    const float* lrb = (const float*)d_in[14];
    const float* lti = (const float*)d_in[15];
    const float* pns = (const float*)d_in[16];
    const float* pnb = (const float*)d_in[17];
    float* out = (float*)d_out;

    float *p_xqk, *p_xv, *p_gate;
    cudaGetSymbolAddress((void**)&p_xqk,  g_xqk);
    cudaGetSymbolAddress((void**)&p_xv,   g_xv);
    cudaGetSymbolAddress((void**)&p_gate, g_gate);

    const int M = Bsz * SEQ;            // 16384
    dim3 gg(WID / 128, M / 128);        // (6, 128)

    sgemm_kernel<<<gg, 256>>>(hidden, wq, p_xqk, M, WID, WID);
    sgemm_kernel<<<gg, 256>>>(hidden, wv, p_xv,  M, WID, WID);
    sgemm_kernel<<<gg, 256>>>(hidden, wg, p_gate, M, WID, WID);
    lr_kernel<<<M / 8, 256>>>(hidden, lrk, lrb);
    conv_rope_kernel<<<(Bsz * SEQ * 384 + 255) / 256, 256>>>(cqk, cqb, ckk, ckb);
    ttt_scan_kernel<<<Bsz * NH, 256>>>(W1, b1, tns, tnb, lti);
    postfuse_kernel<<<M, 256>>>(pns, pnb);
    sgemm_kernel<<<gg, 256>>>(p_gate, wo, out, M, WID, WID);
}

// round 3
// speedup vs baseline: 1.3590x; 1.3590x over previous
#include <cuda_runtime.h>
#include <cuda_bf16.h>
#include <math.h>
#include <stdint.h>

#define Bsz 4
#define SEQ 4096
#define WID 768
#define NH  12
#define MBm 16
#define NBt 256           // SEQ / MBm
#define EPSV 1e-6f
#define MTOT (Bsz*SEQ)    // 16384

// ------------------------- scratch (device globals) -------------------------
__device__ __align__(16) float g_xqk [Bsz*SEQ*WID];
__device__ __align__(16) float g_xv  [Bsz*SEQ*WID];
__device__ __align__(16) float g_gate[Bsz*SEQ*WID];
__device__ __align__(16) float g_xq  [Bsz*SEQ*WID];
__device__ __align__(16) float g_xk  [Bsz*SEQ*WID];
__device__ __align__(16) float g_ttt [Bsz*SEQ*WID];
__device__ __align__(16) float g_lr  [Bsz*NH*SEQ];
__device__ __align__(16) __nv_bfloat16 g_hh[Bsz*SEQ*WID];   // hidden hi
__device__ __align__(16) __nv_bfloat16 g_hl[Bsz*SEQ*WID];   // hidden lo
__device__ __align__(16) __nv_bfloat16 g_th[Bsz*SEQ*WID];   // gate*z hi
__device__ __align__(16) __nv_bfloat16 g_tl[Bsz*SEQ*WID];   // gate*z lo
__device__ __align__(16) __nv_bfloat16 g_wt[8*WID*WID];     // wq_h,wq_l,wv_h,wv_l,wg_h,wg_l,wo_h,wo_l, transposed [N][K]

// ------------------------- helpers -------------------------
__device__ __forceinline__ uint32_t smem_u32(const void* p) {
    uint32_t a;
    asm("{ .reg .u64 t; cvta.to.shared.u64 t, %1; cvt.u32.u64 %0, t; }" : "=r"(a) : "l"(p));
    return a;
}
__device__ __forceinline__ float wred(float v) {
#pragma unroll
    for (int o = 16; o; o >>= 1) v += __shfl_xor_sync(0xffffffffu, v, o);
    return v;
}
__device__ __forceinline__ void cpa16(uint32_t saddr, const void* g) {
    asm volatile("cp.async.cg.shared.global [%0], [%1], 16;" :: "r"(saddr), "l"(g) : "memory");
}
__device__ __forceinline__ void cpa_commit() {
    asm volatile("cp.async.commit_group;" ::: "memory");
}
__device__ __forceinline__ void ldsm4(uint32_t& r0, uint32_t& r1, uint32_t& r2, uint32_t& r3, uint32_t a) {
    asm volatile("ldmatrix.sync.aligned.m8n8.x4.shared.b16 {%0,%1,%2,%3}, [%4];"
                 : "=r"(r0), "=r"(r1), "=r"(r2), "=r"(r3) : "r"(a));
}
__device__ __forceinline__ void mma16816(float* c, const uint32_t* a, const uint32_t* b) {
    asm volatile("mma.sync.aligned.m16n8k16.row.col.f32.bf16.bf16.f32 "
                 "{%0,%1,%2,%3}, {%4,%5,%6,%7}, {%8,%9}, {%0,%1,%2,%3};"
                 : "+f"(c[0]), "+f"(c[1]), "+f"(c[2]), "+f"(c[3])
                 : "r"(a[0]), "r"(a[1]), "r"(a[2]), "r"(a[3]), "r"(b[0]), "r"(b[1]));
}

// ------------------------- fp32 -> bf16 hi/lo split --------------------------
__global__ __launch_bounds__(256) void cvt_hilo_kernel(
    const float* __restrict__ x, __nv_bfloat16* __restrict__ hi,
    __nv_bfloat16* __restrict__ lo, int n4)
{
    int i = blockIdx.x * 256 + threadIdx.x;
    if (i >= n4) return;
    float4 v = ((const float4*)x)[i];
    __nv_bfloat16 h0 = __float2bfloat16(v.x), h1 = __float2bfloat16(v.y);
    __nv_bfloat16 h2 = __float2bfloat16(v.z), h3 = __float2bfloat16(v.w);
    __nv_bfloat16 l0 = __float2bfloat16(v.x - __bfloat162float(h0));
    __nv_bfloat16 l1 = __float2bfloat16(v.y - __bfloat162float(h1));
    __nv_bfloat16 l2 = __float2bfloat16(v.z - __bfloat162float(h2));
    __nv_bfloat16 l3 = __float2bfloat16(v.w - __bfloat162float(h3));
    __nv_bfloat162 ph0(h0, h1), ph1(h2, h3), pl0(l0, l1), pl1(l2, l3);
    ((uint2*)hi)[i] = make_uint2(*(unsigned*)&ph0, *(unsigned*)&ph1);
    ((uint2*)lo)[i] = make_uint2(*(unsigned*)&pl0, *(unsigned*)&pl1);
}

// --------------- weight transpose + split: wt[n][k] = w[k][n], tiled ---------
__global__ __launch_bounds__(256) void cvt_w_kernel(
    const float* __restrict__ w, __nv_bfloat16* __restrict__ th,
    __nv_bfloat16* __restrict__ tl)
{
    __shared__ float tile[32][33];
    const int bx = blockIdx.x * 32;   // n block
    const int by = blockIdx.y * 32;   // k block
    const int x = threadIdx.x, y = threadIdx.y;  // 32 x 8
#pragma unroll
    for (int j = 0; j < 4; j++)
        tile[y + j * 8][x] = w[(size_t)(by + y + j * 8) * WID + bx + x];
    __syncthreads();
#pragma unroll
    for (int j = 0; j < 4; j++) {
        float v = tile[x][y + j * 8];
        __nv_bfloat16 h = __float2bfloat16(v);
        size_t o = (size_t)(bx + y + j * 8) * WID + by + x;
        th[o] = h;
        tl[o] = __float2bfloat16(v - __bfloat162float(h));
    }
}

// ------------------------- bf16-split GEMM via mma.sync ----------------------
// C[M,768](fp32) = A @ W^T-layout-B : A hi/lo [M][768] bf16, B hi/lo [768][768] bf16 [n][k].
// BM=128 BN=128 BK=32, 8 warps (4 M x 2 N), warp tile 32x64. Double-buffered cp.async.
#define TSTRIDE 40        // halves per smem row (32 data + 8 pad) = 80B
#define TILEB  (128*TSTRIDE*2)   // 10240 bytes per tile
#define STAGEB (4*TILEB)         // Ah,Al,Bh,Bl

__global__ __launch_bounds__(256) void mma_gemm_kernel(
    const __nv_bfloat16* __restrict__ Ah, const __nv_bfloat16* __restrict__ Al,
    const __nv_bfloat16* __restrict__ Bh, const __nv_bfloat16* __restrict__ Bl,
    float* __restrict__ C)
{
    extern __shared__ char smem[];
    const uint32_t sb = smem_u32(smem);
    const int tid = threadIdx.x, wid = tid >> 5, lane = tid & 31;
    const int bm = blockIdx.y * 128, bn = blockIdx.x * 128;
    const int warpM = wid & 3, warpN = wid >> 2;

    const __nv_bfloat16* srcs[4] = {
        Ah + (size_t)bm * WID, Al + (size_t)bm * WID,
        Bh + (size_t)bn * WID, Bl + (size_t)bn * WID };

    // load one stage (BK=32 slice at k0) into buffer st
    auto load_stage = [&](int st, int k0) {
#pragma unroll
        for (int t = 0; t < 4; t++) {
#pragma unroll
            for (int rep = 0; rep < 2; rep++) {
                int li = tid + rep * 256;          // 0..511
                int row = li >> 2, cc = li & 3;
                const void* g = srcs[t] + (size_t)row * WID + k0 + cc * 8;
                uint32_t sa = sb + st * STAGEB + t * TILEB + row * (TSTRIDE * 2) + cc * 16;
                cpa16(sa, g);
            }
        }
        cpa_commit();
    };

    float acc[2][8][4];
#pragma unroll
    for (int i = 0; i < 2; i++)
#pragma unroll
        for (int j = 0; j < 8; j++)
#pragma unroll
            for (int k = 0; k < 4; k++) acc[i][j][k] = 0.f;

    load_stage(0, 0);

    const int NK = WID / 32;   // 24
    for (int kt = 0; kt < NK; kt++) {
        if (kt + 1 < NK) load_stage((kt + 1) & 1, (kt + 1) * 32);
        if (kt + 1 < NK) asm volatile("cp.async.wait_group 1;" ::: "memory");
        else             asm volatile("cp.async.wait_group 0;" ::: "memory");
        __syncthreads();

        const uint32_t base = sb + (kt & 1) * STAGEB;
        const int lrow = lane & 15;
        const int lcol = (lane & 16) ? 8 : 0;

#pragma unroll
        for (int kk = 0; kk < 2; kk++) {
            const int kb = kk * 16;
            uint32_t ah[2][4], al[2][4], bh[8][2], bl[8][2];
#pragma unroll
            for (int mt = 0; mt < 2; mt++) {
                uint32_t off = (uint32_t)((warpM * 32 + mt * 16 + lrow) * TSTRIDE + kb + lcol) * 2;
                ldsm4(ah[mt][0], ah[mt][1], ah[mt][2], ah[mt][3], base + 0 * TILEB + off);
                ldsm4(al[mt][0], al[mt][1], al[mt][2], al[mt][3], base + 1 * TILEB + off);
            }
#pragma unroll
            for (int ng = 0; ng < 4; ng++) {
                uint32_t off = (uint32_t)((warpN * 64 + ng * 16 + lrow) * TSTRIDE + kb + lcol) * 2;
                uint32_t r0, r1, r2, r3;
                ldsm4(r0, r1, r2, r3, base + 2 * TILEB + off);
                bh[ng * 2][0] = r0; bh[ng * 2 + 1][0] = r1;
                bh[ng * 2][1] = r2; bh[ng * 2 + 1][1] = r3;
                ldsm4(r0, r1, r2, r3, base + 3 * TILEB + off);
                bl[ng * 2][0] = r0; bl[ng * 2 + 1][0] = r1;
                bl[ng * 2][1] = r2; bl[ng * 2 + 1][1] = r3;
            }
#pragma unroll
            for (int mt = 0; mt < 2; mt++)
#pragma unroll
                for (int nt = 0; nt < 8; nt++) {
                    mma16816(acc[mt][nt], ah[mt], bh[nt]);
                    mma16816(acc[mt][nt], ah[mt], bl[nt]);
                    mma16816(acc[mt][nt], al[mt], bh[nt]);
                }
        }
        __syncthreads();
    }

    // epilogue
    const int r0 = bm + warpM * 32 + (lane >> 2);
    const int cb = bn + warpN * 64 + 2 * (lane & 3);
#pragma unroll
    for (int mt = 0; mt < 2; mt++)
#pragma unroll
        for (int nt = 0; nt < 8; nt++) {
            int row = r0 + mt * 16, col = cb + nt * 8;
            *(float2*)(C + (size_t)row * WID + col) = make_float2(acc[mt][nt][0], acc[mt][nt][1]);
            *(float2*)(C + (size_t)(row + 8) * WID + col) = make_float2(acc[mt][nt][2], acc[mt][nt][3]);
        }
}

// ------------------------- lr logits: sigmoid(hidden . lrk[h] + lrb[h]) / 64 --
__global__ __launch_bounds__(256) void lr_kernel(
    const float* __restrict__ hidden, const float* __restrict__ lrk,
    const float* __restrict__ lrb)
{
    __shared__ float sk[NH * WID];
    const int tid = threadIdx.x;
    for (int i = tid; i < NH * WID; i += 256) sk[i] = lrk[i];
    __syncthreads();

    const int gw = blockIdx.x * 8 + (tid >> 5);
    const int lane = tid & 31;
    const float* hrow = hidden + (size_t)gw * WID;

    float acc[NH];
#pragma unroll
    for (int h = 0; h < NH; h++) acc[h] = 0.f;
    for (int w = lane; w < WID; w += 32) {
        float hv = hrow[w];
#pragma unroll
        for (int h = 0; h < NH; h++) acc[h] += hv * sk[h * WID + w];
    }
    const int b = gw >> 12, n = gw & (SEQ - 1);
#pragma unroll
    for (int h = 0; h < NH; h++) {
        float v = wred(acc[h]);
        if (lane == 0) {
            float x = v + lrb[h];
            g_lr[(size_t)(b * NH + h) * SEQ + n] = (1.f / (1.f + expf(-x))) * (1.f / 64.f);
        }
    }
}

// ------------------------- causal depthwise conv (W=4) + RoPE ---------------
__global__ __launch_bounds__(256) void conv_rope_kernel(
    const float* __restrict__ cqk, const float* __restrict__ cqb,
    const float* __restrict__ ckk, const float* __restrict__ ckb)
{
    int idx = blockIdx.x * blockDim.x + threadIdx.x;
    const int total = Bsz * SEQ * 384;
    if (idx >= total) return;
    int p = idx % 384;
    int n = (idx / 384) % SEQ;
    int b = idx / (384 * SEQ);
    int h = p >> 5;
    int j = p & 31;
    int ce = h * 64 + 2 * j;

    const float* xbase = g_xqk + (size_t)b * SEQ * WID + ce;
    float qe = cqb[ce], qo = cqb[ce + 1];
    float ke = ckb[ce], ko = ckb[ce + 1];
#pragma unroll
    for (int t = 0; t < 4; t++) {
        int nn = n - 3 + t;
        if (nn >= 0) {
            float2 x  = *(const float2*)(xbase + (size_t)nn * WID);
            float2 kq = *(const float2*)(cqk + t * WID + ce);
            float2 kk = *(const float2*)(ckk + t * WID + ce);
            qe += x.x * kq.x; qo += x.y * kq.y;
            ke += x.x * kk.x; ko += x.y * kk.y;
        }
    }
    int pos = n & 15;
    float freq = expf(-9.210340371976184f * (float)j * (1.f / 32.f));
    float ang = (float)pos * freq;
    float c = cosf(ang), s = sinf(ang);
    size_t o = ((size_t)b * SEQ + n) * WID + ce;
    *(float2*)(g_xq + o) = make_float2(qe * c - qo * s, qe * s + qo * c);
    *(float2*)(g_xk + o) = make_float2(ke * c - ko * s, ke * s + ko * c);
}

// ------------------------- TTT scan: one CTA per (b,h) chain -----------------
__global__ __launch_bounds__(256) void ttt_scan_kernel(
    const float* __restrict__ W1in, const float* __restrict__ b1in,
    const float* __restrict__ gin,  const float* __restrict__ bbin,
    const float* __restrict__ lti)
{
    __shared__ float W1s[64 * 64];
    __shared__ float b1s[64], gvs[64], bvs[64];
    __shared__ float sXQ[16 * 68], sXK[16 * 68], sTT[16 * 68], sZ[16 * 68], sZQ[16 * 68], sG[16 * 68];
    __shared__ float Cf[16 * 16];
    __shared__ float lr[16], toki[16], mu[16], rstd[16], s1[16], s2[16];

    const int tid = threadIdx.x;
    const int bh = blockIdx.x;
    const int b = bh / NH, h = bh % NH;

    for (int i = tid; i < 4096; i += 256) W1s[i] = W1in[h * 4096 + i];
    if (tid < 64) {
        b1s[tid] = b1in[h * 64 + tid];
        gvs[tid] = gin[h * 64 + tid];
        bvs[tid] = bbin[h * 64 + tid];
    }
    if (tid < 16) toki[tid] = fmaxf(1.f / (float)(tid + 1) + lti[tid], 0.f);

    const int r = tid >> 4;
    const int c0 = (tid & 15) * 4;
    const int lane = tid & 31, wid = tid >> 5;
    const size_t gbase = (size_t)b * SEQ * WID + h * 64;
    const float* lrp = g_lr + (size_t)bh * SEQ;

    __syncthreads();

    for (int nb = 0; nb < NBt; nb++) {
        const size_t off = gbase + (size_t)(nb * MBm + r) * WID + c0;
        float4 q4 = *(const float4*)(g_xq + off);
        float4 k4 = *(const float4*)(g_xk + off);
        float4 v4 = *(const float4*)(g_xv + off);
        __syncthreads();
        *(float4*)(sXQ + r * 68 + c0) = q4;
        *(float4*)(sXK + r * 68 + c0) = k4;
        *(float4*)(sTT + r * 68 + c0) = make_float4(v4.x - k4.x, v4.y - k4.y,
                                                    v4.z - k4.z, v4.w - k4.w);
        if (tid < 16) lr[tid] = lrp[nb * MBm + tid];
        __syncthreads();

        // coef[i][m] = eta[i][m]*(Attn[i][m]+1) for m<=i
        {
            const int i = r, m = tid & 15;
            float cf = 0.f;
            if (m <= i) {
                float d = 0.f;
#pragma unroll 8
                for (int k = 0; k < 64; k++) d += sXQ[i * 68 + k] * sXK[m * 68 + k];
                cf = toki[i] * lr[m] * (d + 1.f);
            }
            Cf[i * 16 + m] = cf;
        }
        // fused: Z1 = XK@W1 + b1,  ZQ = XQ@W1 + b1  (one W1 read)
        {
            float4 acck = make_float4(b1s[c0], b1s[c0 + 1], b1s[c0 + 2], b1s[c0 + 3]);
            float4 accq = acck;
#pragma unroll 8
            for (int k = 0; k < 64; k++) {
                float xk = sXK[r * 68 + k];
                float xq = sXQ[r * 68 + k];
                float4 w = *(const float4*)(W1s + k * 64 + c0);
                acck.x = fmaf(xk, w.x, acck.x); acck.y = fmaf(xk, w.y, acck.y);
                acck.z = fmaf(xk, w.z, acck.z); acck.w = fmaf(xk, w.w, acck.w);
                accq.x = fmaf(xq, w.x, accq.x); accq.y = fmaf(xq, w.y, accq.y);
                accq.z = fmaf(xq, w.z, accq.z); accq.w = fmaf(xq, w.w, accq.w);
            }
            *(float4*)(sZ  + r * 68 + c0) = acck;
            *(float4*)(sZQ + r * 68 + c0) = accq;
        }
        __syncthreads();

        // row stats of Z1
        for (int rr = wid; rr < 16; rr += 8) {
            float x0 = sZ[rr * 68 + lane], x1 = sZ[rr * 68 + lane + 32];
            float s = wred(x0 + x1);
            float q = wred(x0 * x0 + x1 * x1);
            if (lane == 0) {
                float m = s * (1.f / 64.f);
                mu[rr] = m;
                rstd[rr] = rsqrtf(q * (1.f / 64.f) - m * m + EPSV);
            }
        }
        __syncthreads();

        // gxh = (g*x_hat + b - target) * g
        {
            float m = mu[r], rs = rstd[r];
            float4 z = *(const float4*)(sZ + r * 68 + c0);
            float4 t = *(const float4*)(sTT + r * 68 + c0);
            float g0 = gvs[c0], g1 = gvs[c0 + 1], g2 = gvs[c0 + 2], g3 = gvs[c0 + 3];
            float b0 = bvs[c0], b1v = bvs[c0 + 1], b2 = bvs[c0 + 2], b3 = bvs[c0 + 3];
            float4 gx;
            gx.x = (g0 * ((z.x - m) * rs) + b0 - t.x) * g0;
            gx.y = (g1 * ((z.y - m) * rs) + b1v - t.y) * g1;
            gx.z = (g2 * ((z.z - m) * rs) + b2 - t.z) * g2;
            gx.w = (g3 * ((z.w - m) * rs) + b3 - t.w) * g3;
            *(float4*)(sG + r * 68 + c0) = gx;
        }
        __syncthreads();

        // sum(gxh), sum(gxh * x_hat)
        for (int rr = wid; rr < 16; rr += 8) {
            float m = mu[rr], rs = rstd[rr];
            float a0 = sG[rr * 68 + lane], a1 = sG[rr * 68 + lane + 32];
            float xh0 = (sZ[rr * 68 + lane] - m) * rs;
            float xh1 = (sZ[rr * 68 + lane + 32] - m) * rs;
            float sa = wred(a0 + a1);
            float sb = wred(a0 * xh0 + a1 * xh1);
            if (lane == 0) { s1[rr] = sa; s2[rr] = sb; }
        }
        __syncthreads();

        // grad = (64*gxh - s1 - x_hat*s2) * rstd/64
        {
            float m = mu[r], rs = rstd[r], sa = s1[r], sb = s2[r], sc = rs * (1.f / 64.f);
            float4 z = *(const float4*)(sZ + r * 68 + c0);
            float4 gx = *(const float4*)(sG + r * 68 + c0);
            float4 gr;
            gr.x = (64.f * gx.x - sa - ((z.x - m) * rs) * sb) * sc;
            gr.y = (64.f * gx.y - sa - ((z.y - m) * rs) * sb) * sc;
            gr.z = (64.f * gx.z - sa - ((z.z - m) * rs) * sb) * sc;
            gr.w = (64.f * gx.w - sa - ((z.w - m) * rs) * sb) * sc;
            *(float4*)(sG + r * 68 + c0) = gr;
        }
        __syncthreads();

        // Z1_bar = ZQ - coef@grad
        {
            float4 acc = *(const float4*)(sZQ + r * 68 + c0);
#pragma unroll
            for (int m = 0; m < 16; m++) {
                float cf = Cf[r * 16 + m];
                float4 g = *(const float4*)(sG + m * 68 + c0);
                acc.x -= cf * g.x; acc.y -= cf * g.y;
                acc.z -= cf * g.z; acc.w -= cf * g.w;
            }
            *(float4*)(sZ + r * 68 + c0) = acc;
        }
        __syncthreads();

        // stats of Z1_bar  +  W1/b1 update
        for (int rr = wid; rr < 16; rr += 8) {
            float x0 = sZ[rr * 68 + lane], x1 = sZ[rr * 68 + lane + 32];
            float s = wred(x0 + x1);
            float q = wred(x0 * x0 + x1 * x1);
            if (lane == 0) {
                float m = s * (1.f / 64.f);
                mu[rr] = m;
                rstd[rr] = rsqrtf(q * (1.f / 64.f) - m * m + EPSV);
            }
        }
        {
            const int d = tid & 63;
            const float let15 = toki[15];
            float gvv[16];
            float bs = 0.f;
#pragma unroll
            for (int m = 0; m < 16; m++) {
                gvv[m] = let15 * lr[m] * sG[m * 68 + d];
                bs += gvv[m];
            }
            const int kb = tid >> 6;
#pragma unroll
            for (int jj = 0; jj < 16; jj++) {
                int k = kb + 4 * jj;
                float s = 0.f;
#pragma unroll
                for (int m = 0; m < 16; m++) s += sXK[m * 68 + k] * gvv[m];
                W1s[k * 64 + d] -= s;
            }
            if (tid < 64) b1s[tid] -= bs;
        }
        __syncthreads();

        // out = XQ + ln_fwd(Z1_bar)
        {
            float m = mu[r], rs = rstd[r];
            float4 z = *(const float4*)(sZ + r * 68 + c0);
            float4 q = *(const float4*)(sXQ + r * 68 + c0);
            float4 o;
            o.x = q.x + gvs[c0 + 0] * ((z.x - m) * rs) + bvs[c0 + 0];
            o.y = q.y + gvs[c0 + 1] * ((z.y - m) * rs) + bvs[c0 + 1];
            o.z = q.z + gvs[c0 + 2] * ((z.z - m) * rs) + bvs[c0 + 2];
            o.w = q.w + gvs[c0 + 3] * ((z.w - m) * rs) + bvs[c0 + 3];
            *(float4*)(g_ttt + off) = o;
        }
    }
}

// ------------------------- post: t = gelu(gate) * LN(out) -> bf16 hi/lo -----
__global__ __launch_bounds__(256) void postfuse_kernel(
    const float* __restrict__ pns, const float* __restrict__ pnb)
{
    __shared__ float ws[8], wq2[8];
    __shared__ float smu, srs;
    const int row = blockIdx.x;
    const int tid = threadIdx.x;
    const int lane = tid & 31, wid = tid >> 5;
    const float* o = g_ttt + (size_t)row * WID;
    const float* gp = g_gate + (size_t)row * WID;

    float v[3], s = 0.f, q = 0.f;
#pragma unroll
    for (int i = 0; i < 3; i++) {
        v[i] = o[tid + i * 256];
        s += v[i]; q += v[i] * v[i];
    }
    s = wred(s); q = wred(q);
    if (lane == 0) { ws[wid] = s; wq2[wid] = q; }
    __syncthreads();
    if (tid == 0) {
        float S = 0.f, Q = 0.f;
#pragma unroll
        for (int i = 0; i < 8; i++) { S += ws[i]; Q += wq2[i]; }
        float m = S * (1.f / 768.f);
        smu = m;
        srs = rsqrtf(Q * (1.f / 768.f) - m * m + EPSV);
    }
    __syncthreads();
    const float m = smu, rs = srs;
#pragma unroll
    for (int i = 0; i < 3; i++) {
        int c = tid + i * 256;
        float z = pns[c] * ((v[i] - m) * rs) + pnb[c];
        float x = gp[c];
        float gl = 0.5f * x * (1.f + tanhf(0.7978845608028654f * (x + 0.044715f * x * x * x)));
        float val = gl * z;
        __nv_bfloat16 hi = __float2bfloat16(val);
        g_th[(size_t)row * WID + c] = hi;
        g_tl[(size_t)row * WID + c] = __float2bfloat16(val - __bfloat162float(hi));
    }
}

// ------------------------- launch --------------------------------------------
extern "C" void kernel_launch(void* const* d_in, const int* in_sizes, int n_in,
                              void* d_out, int out_size)
{
    const float* hidden = (const float*)d_in[0];
    const float* wq  = (const float*)d_in[1];
    const float* wv  = (const float*)d_in[2];
    const float* wo  = (const float*)d_in[3];
    const float* wg  = (const float*)d_in[4];
    const float* cqk = (const float*)d_in[5];
    const float* cqb = (const float*)d_in[6];
    const float* ckk = (const float*)d_in[7];
    const float* ckb = (const float*)d_in[8];
    const float* W1  = (const float*)d_in[9];
    const float* b1  = (const float*)d_in[10];
    const float* tns = (const float*)d_in[11];
    const float* tnb = (const float*)d_in[12];
    const float* lrk = (const float*)d_in[13];
    const float* lrb = (const float*)d_in[14];
    const float* lti = (const float*)d_in[15];
    const float* pns = (const float*)d_in[16];
    const float* pnb = (const float*)d_in[17];
    float* out = (float*)d_out;

    float *p_xqk, *p_xv, *p_gate;
    __nv_bfloat16 *p_hh, *p_hl, *p_th, *p_tl, *p_wt;
    cudaGetSymbolAddress((void**)&p_xqk,  g_xqk);
    cudaGetSymbolAddress((void**)&p_xv,   g_xv);
    cudaGetSymbolAddress((void**)&p_gate, g_gate);
    cudaGetSymbolAddress((void**)&p_hh,   g_hh);
    cudaGetSymbolAddress((void**)&p_hl,   g_hl);
    cudaGetSymbolAddress((void**)&p_th,   g_th);
    cudaGetSymbolAddress((void**)&p_tl,   g_tl);
    cudaGetSymbolAddress((void**)&p_wt,   g_wt);

    const int smem_mma = 2 * STAGEB;   // 81920
    cudaFuncSetAttribute(mma_gemm_kernel, cudaFuncAttributeMaxDynamicSharedMemorySize, smem_mma);

    const int WW = WID * WID;
    cvt_hilo_kernel<<<(MTOT * WID / 4 + 255) / 256, 256>>>(hidden, p_hh, p_hl, MTOT * WID / 4);
    dim3 tb(32, 8), tg(WID / 32, WID / 32);
    cvt_w_kernel<<<tg, tb>>>(wq, p_wt + 0 * WW, p_wt + 1 * WW);
    cvt_w_kernel<<<tg, tb>>>(wv, p_wt + 2 * WW, p_wt + 3 * WW);
    cvt_w_kernel<<<tg, tb>>>(wg, p_wt + 4 * WW, p_wt + 5 * WW);
    cvt_w_kernel<<<tg, tb>>>(wo, p_wt + 6 * WW, p_wt + 7 * WW);

    dim3 gg(WID / 128, MTOT / 128);   // (6, 128)
    mma_gemm_kernel<<<gg, 256, smem_mma>>>(p_hh, p_hl, p_wt + 0 * WW, p_wt + 1 * WW, p_xqk);
    mma_gemm_kernel<<<gg, 256, smem_mma>>>(p_hh, p_hl, p_wt + 2 * WW, p_wt + 3 * WW, p_xv);
    mma_gemm_kernel<<<gg, 256, smem_mma>>>(p_hh, p_hl, p_wt + 4 * WW, p_wt + 5 * WW, p_gate);

    lr_kernel<<<MTOT / 8, 256>>>(hidden, lrk, lrb);
    conv_rope_kernel<<<(Bsz * SEQ * 384 + 255) / 256, 256>>>(cqk, cqb, ckk, ckb);
    ttt_scan_kernel<<<Bsz * NH, 256>>>(W1, b1, tns, tnb, lti);
    postfuse_kernel<<<MTOT, 256>>>(pns, pnb);
    mma_gemm_kernel<<<gg, 256, smem_mma>>>(p_th, p_tl, p_wt + 6 * WW, p_wt + 7 * WW, out);
}

// round 4
// speedup vs baseline: 2.0513x; 1.5094x over previous
#include <cuda_runtime.h>
#include <cuda_bf16.h>
#include <math.h>
#include <stdint.h>

#define Bsz 4
#define SEQ 4096
#define WID 768
#define NH  12
#define MBm 16
#define NBt 256           // SEQ / MBm
#define EPSV 1e-6f
#define MTOT (Bsz*SEQ)    // 16384
#define WW   (WID*WID)

// ------------------------- scratch (device globals) -------------------------
__device__ __align__(16) float g_xqk [Bsz*SEQ*WID];
__device__ __align__(16) float g_xv  [Bsz*SEQ*WID];
__device__ __align__(16) float g_gate[Bsz*SEQ*WID];
__device__ __align__(16) float g_xq  [Bsz*SEQ*WID];
__device__ __align__(16) float g_xk  [Bsz*SEQ*WID];
__device__ __align__(16) float g_ttt [Bsz*SEQ*WID];
__device__ __align__(16) float g_lr  [Bsz*NH*SEQ];
__device__ __align__(16) __nv_bfloat16 g_hh[Bsz*SEQ*WID];   // hidden hi
__device__ __align__(16) __nv_bfloat16 g_hl[Bsz*SEQ*WID];   // hidden lo
__device__ __align__(16) __nv_bfloat16 g_th[Bsz*SEQ*WID];   // gate*z hi
__device__ __align__(16) __nv_bfloat16 g_tl[Bsz*SEQ*WID];   // gate*z lo
// layout: [0,3WW): hi of {wq,wv,wg} stacked [2304][768]; [3WW,6WW): lo stacked;
//         [6WW): wo hi; [7WW): wo lo.  All transposed [n][k].
__device__ __align__(16) __nv_bfloat16 g_wt[8*WW];

// ------------------------- helpers -------------------------
__device__ __forceinline__ uint32_t smem_u32(const void* p) {
    uint32_t a;
    asm("{ .reg .u64 t; cvta.to.shared.u64 t, %1; cvt.u32.u64 %0, t; }" : "=r"(a) : "l"(p));
    return a;
}
__device__ __forceinline__ float wred(float v) {
#pragma unroll
    for (int o = 16; o; o >>= 1) v += __shfl_xor_sync(0xffffffffu, v, o);
    return v;
}
__device__ __forceinline__ float hred(float v) {   // half-warp (16-lane) reduce
#pragma unroll
    for (int o = 8; o; o >>= 1) v += __shfl_xor_sync(0xffffffffu, v, o);
    return v;
}
__device__ __forceinline__ unsigned long long pk2(float lo, float hi) {
    unsigned long long r;
    asm("mov.b64 %0, {%1, %2};" : "=l"(r) : "f"(lo), "f"(hi));
    return r;
}
__device__ __forceinline__ void fma2(unsigned long long& acc,
                                     unsigned long long a, unsigned long long b) {
    asm("fma.rn.f32x2 %0, %1, %2, %0;" : "+l"(acc) : "l"(a), "l"(b));
}
__device__ __forceinline__ float2 up2(unsigned long long v) {
    float lo, hi;
    asm("mov.b64 {%0, %1}, %2;" : "=f"(lo), "=f"(hi) : "l"(v));
    return make_float2(lo, hi);
}
__device__ __forceinline__ void cpa16(uint32_t saddr, const void* g) {
    asm volatile("cp.async.cg.shared.global [%0], [%1], 16;" :: "r"(saddr), "l"(g) : "memory");
}
__device__ __forceinline__ void cpa_commit() {
    asm volatile("cp.async.commit_group;" ::: "memory");
}
__device__ __forceinline__ void ldsm4(uint32_t& r0, uint32_t& r1, uint32_t& r2, uint32_t& r3, uint32_t a) {
    asm volatile("ldmatrix.sync.aligned.m8n8.x4.shared.b16 {%0,%1,%2,%3}, [%4];"
                 : "=r"(r0), "=r"(r1), "=r"(r2), "=r"(r3) : "r"(a));
}
__device__ __forceinline__ void mma16816(float* c, const uint32_t* a, const uint32_t* b) {
    asm volatile("mma.sync.aligned.m16n8k16.row.col.f32.bf16.bf16.f32 "
                 "{%0,%1,%2,%3}, {%4,%5,%6,%7}, {%8,%9}, {%0,%1,%2,%3};"
                 : "+f"(c[0]), "+f"(c[1]), "+f"(c[2]), "+f"(c[3])
                 : "r"(a[0]), "r"(a[1]), "r"(a[2]), "r"(a[3]), "r"(b[0]), "r"(b[1]));
}

// ------------------------- fp32 -> bf16 hi/lo split --------------------------
__global__ __launch_bounds__(256) void cvt_hilo_kernel(
    const float* __restrict__ x, __nv_bfloat16* __restrict__ hi,
    __nv_bfloat16* __restrict__ lo, int n4)
{
    int i = blockIdx.x * 256 + threadIdx.x;
    if (i >= n4) return;
    float4 v = ((const float4*)x)[i];
    __nv_bfloat16 h0 = __float2bfloat16(v.x), h1 = __float2bfloat16(v.y);
    __nv_bfloat16 h2 = __float2bfloat16(v.z), h3 = __float2bfloat16(v.w);
    __nv_bfloat16 l0 = __float2bfloat16(v.x - __bfloat162float(h0));
    __nv_bfloat16 l1 = __float2bfloat16(v.y - __bfloat162float(h1));
    __nv_bfloat16 l2 = __float2bfloat16(v.z - __bfloat162float(h2));
    __nv_bfloat16 l3 = __float2bfloat16(v.w - __bfloat162float(h3));
    __nv_bfloat162 ph0(h0, h1), ph1(h2, h3), pl0(l0, l1), pl1(l2, l3);
    ((uint2*)hi)[i] = make_uint2(*(unsigned*)&ph0, *(unsigned*)&ph1);
    ((uint2*)lo)[i] = make_uint2(*(unsigned*)&pl0, *(unsigned*)&pl1);
}

// --------------- weight transpose + split, all 4 weights in one launch ------
__global__ __launch_bounds__(256) void cvt_w_kernel(
    const float* __restrict__ w0, const float* __restrict__ w1,
    const float* __restrict__ w2, const float* __restrict__ w3)
{
    __shared__ float tile[32][33];
    const int z = blockIdx.z;
    const float* w = (z == 0) ? w0 : (z == 1) ? w1 : (z == 2) ? w2 : w3;
    __nv_bfloat16* th = g_wt + ((z < 3) ? (size_t)z * WW : (size_t)6 * WW);
    __nv_bfloat16* tl = g_wt + ((z < 3) ? (size_t)(3 + z) * WW : (size_t)7 * WW);
    const int bx = blockIdx.x * 32;   // n block
    const int by = blockIdx.y * 32;   // k block
    const int x = threadIdx.x, y = threadIdx.y;  // 32 x 8
#pragma unroll
    for (int j = 0; j < 4; j++)
        tile[y + j * 8][x] = w[(size_t)(by + y + j * 8) * WID + bx + x];
    __syncthreads();
#pragma unroll
    for (int j = 0; j < 4; j++) {
        float v = tile[x][y + j * 8];
        __nv_bfloat16 h = __float2bfloat16(v);
        size_t o = (size_t)(bx + y + j * 8) * WID + by + x;
        th[o] = h;
        tl[o] = __float2bfloat16(v - __bfloat162float(h));
    }
}

// ------------------------- bf16-split GEMM via mma.sync ----------------------
// A hi/lo [M][768]; B hi/lo stacked [Nb][768] ([n][k]); output tile column
// selects one of up to three C buffers (each [M][768]).
#define TSTRIDE 40        // halves per smem row (32 data + 8 pad) = 80B
#define TILEB  (128*TSTRIDE*2)   // 10240 bytes per tile
#define STAGEB (4*TILEB)

__global__ __launch_bounds__(256) void mma_gemm_kernel(
    const __nv_bfloat16* __restrict__ Ah, const __nv_bfloat16* __restrict__ Al,
    const __nv_bfloat16* __restrict__ Bh, const __nv_bfloat16* __restrict__ Bl,
    float* __restrict__ C0, float* __restrict__ C1, float* __restrict__ C2)
{
    extern __shared__ char smem[];
    const uint32_t sb = smem_u32(smem);
    const int tid = threadIdx.x, wid = tid >> 5, lane = tid & 31;
    const int bm = blockIdx.y * 128;
    const int bn = blockIdx.x * 128;             // within the stacked N
    const int buf = blockIdx.x / 6;
    const int coloff = (blockIdx.x % 6) * 128;
    float* C = (buf == 0) ? C0 : (buf == 1) ? C1 : C2;
    const int warpM = wid & 3, warpN = wid >> 2;

    const __nv_bfloat16* srcs[4] = {
        Ah + (size_t)bm * WID, Al + (size_t)bm * WID,
        Bh + (size_t)bn * WID, Bl + (size_t)bn * WID };

    auto load_stage = [&](int st, int k0) {
#pragma unroll
        for (int t = 0; t < 4; t++) {
#pragma unroll
            for (int rep = 0; rep < 2; rep++) {
                int li = tid + rep * 256;
                int row = li >> 2, cc = li & 3;
                const void* g = srcs[t] + (size_t)row * WID + k0 + cc * 8;
                uint32_t sa = sb + st * STAGEB + t * TILEB + row * (TSTRIDE * 2) + cc * 16;
                cpa16(sa, g);
            }
        }
        cpa_commit();
    };

    float acc[2][8][4];
#pragma unroll
    for (int i = 0; i < 2; i++)
#pragma unroll
        for (int j = 0; j < 8; j++)
#pragma unroll
            for (int k = 0; k < 4; k++) acc[i][j][k] = 0.f;

    load_stage(0, 0);

    const int NK = WID / 32;   // 24
    for (int kt = 0; kt < NK; kt++) {
        if (kt + 1 < NK) load_stage((kt + 1) & 1, (kt + 1) * 32);
        if (kt + 1 < NK) asm volatile("cp.async.wait_group 1;" ::: "memory");
        else             asm volatile("cp.async.wait_group 0;" ::: "memory");
        __syncthreads();

        const uint32_t base = sb + (kt & 1) * STAGEB;
        const int lrow = lane & 15;
        const int lcol = (lane & 16) ? 8 : 0;

#pragma unroll
        for (int kk = 0; kk < 2; kk++) {
            const int kb = kk * 16;
            uint32_t ah[2][4], al[2][4], bh[8][2], bl[8][2];
#pragma unroll
            for (int mt = 0; mt < 2; mt++) {
                uint32_t off = (uint32_t)((warpM * 32 + mt * 16 + lrow) * TSTRIDE + kb + lcol) * 2;
                ldsm4(ah[mt][0], ah[mt][1], ah[mt][2], ah[mt][3], base + 0 * TILEB + off);
                ldsm4(al[mt][0], al[mt][1], al[mt][2], al[mt][3], base + 1 * TILEB + off);
            }
#pragma unroll
            for (int ng = 0; ng < 4; ng++) {
                uint32_t off = (uint32_t)((warpN * 64 + ng * 16 + lrow) * TSTRIDE + kb + lcol) * 2;
                uint32_t r0, r1, r2, r3;
                ldsm4(r0, r1, r2, r3, base + 2 * TILEB + off);
                bh[ng * 2][0] = r0; bh[ng * 2 + 1][0] = r1;
                bh[ng * 2][1] = r2; bh[ng * 2 + 1][1] = r3;
                ldsm4(r0, r1, r2, r3, base + 3 * TILEB + off);
                bl[ng * 2][0] = r0; bl[ng * 2 + 1][0] = r1;
                bl[ng * 2][1] = r2; bl[ng * 2 + 1][1] = r3;
            }
#pragma unroll
            for (int mt = 0; mt < 2; mt++)
#pragma unroll
                for (int nt = 0; nt < 8; nt++) {
                    mma16816(acc[mt][nt], ah[mt], bh[nt]);
                    mma16816(acc[mt][nt], ah[mt], bl[nt]);
                    mma16816(acc[mt][nt], al[mt], bh[nt]);
                }
        }
        __syncthreads();
    }

    const int r0 = bm + warpM * 32 + (lane >> 2);
    const int cb = coloff + warpN * 64 + 2 * (lane & 3);
#pragma unroll
    for (int mt = 0; mt < 2; mt++)
#pragma unroll
        for (int nt = 0; nt < 8; nt++) {
            int row = r0 + mt * 16, col = cb + nt * 8;
            *(float2*)(C + (size_t)row * WID + col) = make_float2(acc[mt][nt][0], acc[mt][nt][1]);
            *(float2*)(C + (size_t)(row + 8) * WID + col) = make_float2(acc[mt][nt][2], acc[mt][nt][3]);
        }
}

// ------------------------- lr logits -----------------------------------------
__global__ __launch_bounds__(256) void lr_kernel(
    const float* __restrict__ hidden, const float* __restrict__ lrk,
    const float* __restrict__ lrb)
{
    __shared__ float sk[NH * WID];
    const int tid = threadIdx.x;
    for (int i = tid; i < NH * WID; i += 256) sk[i] = lrk[i];
    __syncthreads();

    const int gw = blockIdx.x * 8 + (tid >> 5);
    const int lane = tid & 31;
    const float* hrow = hidden + (size_t)gw * WID;

    float acc[NH];
#pragma unroll
    for (int h = 0; h < NH; h++) acc[h] = 0.f;
    for (int w = lane; w < WID; w += 32) {
        float hv = hrow[w];
#pragma unroll
        for (int h = 0; h < NH; h++) acc[h] += hv * sk[h * WID + w];
    }
    const int b = gw >> 12, n = gw & (SEQ - 1);
#pragma unroll
    for (int h = 0; h < NH; h++) {
        float v = wred(acc[h]);
        if (lane == 0) {
            float x = v + lrb[h];
            g_lr[(size_t)(b * NH + h) * SEQ + n] = (1.f / (1.f + expf(-x))) * (1.f / 64.f);
        }
    }
}

// ------------------------- causal depthwise conv (W=4) + RoPE ---------------
__global__ __launch_bounds__(256) void conv_rope_kernel(
    const float* __restrict__ cqk, const float* __restrict__ cqb,
    const float* __restrict__ ckk, const float* __restrict__ ckb)
{
    int idx = blockIdx.x * blockDim.x + threadIdx.x;
    const int total = Bsz * SEQ * 384;
    if (idx >= total) return;
    int p = idx % 384;
    int n = (idx / 384) % SEQ;
    int b = idx / (384 * SEQ);
    int h = p >> 5;
    int j = p & 31;
    int ce = h * 64 + 2 * j;

    const float* xbase = g_xqk + (size_t)b * SEQ * WID + ce;
    float qe = cqb[ce], qo = cqb[ce + 1];
    float ke = ckb[ce], ko = ckb[ce + 1];
#pragma unroll
    for (int t = 0; t < 4; t++) {
        int nn = n - 3 + t;
        if (nn >= 0) {
            float2 x  = *(const float2*)(xbase + (size_t)nn * WID);
            float2 kq = *(const float2*)(cqk + t * WID + ce);
            float2 kk = *(const float2*)(ckk + t * WID + ce);
            qe += x.x * kq.x; qo += x.y * kq.y;
            ke += x.x * kk.x; ko += x.y * kk.y;
        }
    }
    int pos = n & 15;
    float freq = expf(-9.210340371976184f * (float)j * (1.f / 32.f));
    float ang = (float)pos * freq;
    float c = cosf(ang), s = sinf(ang);
    size_t o = ((size_t)b * SEQ + n) * WID + ce;
    *(float2*)(g_xq + o) = make_float2(qe * c - qo * s, qe * s + qo * c);
    *(float2*)(g_xk + o) = make_float2(ke * c - ko * s, ke * s + ko * c);
}

// ------------------------- TTT scan: one CTA per (b,h) chain -----------------
// 256 threads: thread = (row r = tid>>4, colgroup c0 = (tid&15)*4).
// Row r lives in one half-warp -> LN reductions via shfl, 3 syncthreads/step.
__global__ __launch_bounds__(256) void ttt_scan_kernel(
    const float* __restrict__ W1in, const float* __restrict__ b1in,
    const float* __restrict__ gin,  const float* __restrict__ bbin,
    const float* __restrict__ lti)
{
    __shared__ float W1s[64 * 64];
    __shared__ float b1s[64];
    __shared__ float sXQ[16 * 68], sXK[16 * 68], sG[16 * 68];
    __shared__ float Cf[256];
    __shared__ float lr[16], lrw[16], toki[16];

    const int tid = threadIdx.x;
    const int bh = blockIdx.x;
    const int b = bh / NH, h = bh % NH;

    for (int i = tid; i < 4096; i += 256) W1s[i] = W1in[h * 4096 + i];
    if (tid < 64) b1s[tid] = b1in[h * 64 + tid];
    if (tid < 16) toki[tid] = fmaxf(1.f / (float)(tid + 1) + lti[tid], 0.f);

    const int r = tid >> 4;
    const int cg = tid & 15;
    const int c0 = cg * 4;
    const size_t gbase = (size_t)b * SEQ * WID + h * 64;
    const float* lrp = g_lr + (size_t)bh * SEQ;

    // LN params cached in regs
    const float gv0 = gin[h * 64 + c0],     gv1 = gin[h * 64 + c0 + 1];
    const float gv2 = gin[h * 64 + c0 + 2], gv3 = gin[h * 64 + c0 + 3];
    const float bv0 = bbin[h * 64 + c0],     bv1 = bbin[h * 64 + c0 + 1];
    const float bv2 = bbin[h * 64 + c0 + 2], bv3 = bbin[h * 64 + c0 + 3];

    __syncthreads();
    const float tokir = toki[r];
    const float toki15 = toki[15];

    // prefetch nb = 0
    size_t offn = gbase + (size_t)r * WID + c0;
    float4 q4n = *(const float4*)(g_xq + offn);
    float4 k4n = *(const float4*)(g_xk + offn);
    float4 v4n = *(const float4*)(g_xv + offn);
    float lrn = (tid < 16) ? lrp[tid] : 0.f;

    for (int nb = 0; nb < NBt; nb++) {
        const float4 q4 = q4n, k4 = k4n, v4 = v4n;
        const size_t offc = gbase + (size_t)(nb * MBm + r) * WID + c0;

        __syncthreads();                       // (A) prior-step readers done
        *(float4*)(sXQ + r * 68 + c0) = q4;
        *(float4*)(sXK + r * 68 + c0) = k4;
        if (tid < 16) { lr[tid] = lrn; lrw[tid] = toki15 * lrn; }
        __syncthreads();                       // (B)

        if (nb + 1 < NBt) {
            size_t o2 = gbase + (size_t)((nb + 1) * MBm + r) * WID + c0;
            q4n = *(const float4*)(g_xq + o2);
            k4n = *(const float4*)(g_xk + o2);
            v4n = *(const float4*)(g_xv + o2);
            lrn = (tid < 16) ? lrp[(nb + 1) * MBm + tid] : 0.f;
        }

        // Cf[i=r][m=cg] = toki[r]*lr[m]*(XQ[r].XK[m] + 1), m<=r
        {
            float cf = 0.f;
            if (cg <= r) {
                unsigned long long acc = 0ULL;
#pragma unroll 8
                for (int kk = 0; kk < 32; kk++) {
                    unsigned long long a = *(const unsigned long long*)(sXQ + r * 68 + 2 * kk);
                    unsigned long long bb = *(const unsigned long long*)(sXK + cg * 68 + 2 * kk);
                    fma2(acc, a, bb);
                }
                float2 p = up2(acc);
                cf = tokir * lr[cg] * (p.x + p.y + 1.f);
            }
            Cf[r * 16 + cg] = cf;
        }

        // dual GEMM: Z1 = XK@W1 + b1 (accK), ZQ = XQ@W1 + b1 (accQ)
        unsigned long long aK0, aK1, aQ0, aQ1;
        {
            float2 b01 = *(const float2*)(b1s + c0);
            float2 b23 = *(const float2*)(b1s + c0 + 2);
            aK0 = pk2(b01.x, b01.y); aK1 = pk2(b23.x, b23.y);
            aQ0 = aK0; aQ1 = aK1;
        }
#pragma unroll 8
        for (int k = 0; k < 64; k++) {
            float xk = sXK[r * 68 + k];
            float xq = sXQ[r * 68 + k];
            ulonglong2 w = *(const ulonglong2*)(W1s + k * 64 + c0);
            unsigned long long pk = pk2(xk, xk), pq = pk2(xq, xq);
            fma2(aK0, pk, w.x); fma2(aK1, pk, w.y);
            fma2(aQ0, pq, w.x); fma2(aQ1, pq, w.y);
        }

        // LN-fused-L2-bwd, all in regs + half-warp shuffles
        {
            float2 zA = up2(aK0), zB = up2(aK1);
            float z0 = zA.x, z1 = zA.y, z2 = zB.x, z3 = zB.y;
            float t0 = v4.x - k4.x, t1 = v4.y - k4.y, t2 = v4.z - k4.z, t3 = v4.w - k4.w;
            float s = hred(z0 + z1 + z2 + z3);
            float qq = hred(z0 * z0 + z1 * z1 + z2 * z2 + z3 * z3);
            float m = s * (1.f / 64.f);
            float rstd = rsqrtf(qq * (1.f / 64.f) - m * m + EPSV);
            float xh0 = (z0 - m) * rstd, xh1 = (z1 - m) * rstd;
            float xh2 = (z2 - m) * rstd, xh3 = (z3 - m) * rstd;
            float gx0 = (gv0 * xh0 + bv0 - t0) * gv0;
            float gx1 = (gv1 * xh1 + bv1 - t1) * gv1;
            float gx2 = (gv2 * xh2 + bv2 - t2) * gv2;
            float gx3 = (gv3 * xh3 + bv3 - t3) * gv3;
            float s1 = hred(gx0 + gx1 + gx2 + gx3);
            float s2 = hred(gx0 * xh0 + gx1 * xh1 + gx2 * xh2 + gx3 * xh3);
            float sc = rstd * (1.f / 64.f);
            float4 gr;
            gr.x = (64.f * gx0 - s1 - xh0 * s2) * sc;
            gr.y = (64.f * gx1 - s1 - xh1 * s2) * sc;
            gr.z = (64.f * gx2 - s1 - xh2 * s2) * sc;
            gr.w = (64.f * gx3 - s1 - xh3 * s2) * sc;
            *(float4*)(sG + r * 68 + c0) = gr;
        }
        __syncthreads();                       // (C) sG + Cf complete

        // Z1_bar = ZQ - Cf@grad ; then out = XQ + ln_fwd(Z1_bar)
        {
#pragma unroll
            for (int mm = 0; mm < 16; mm++) {
                float cf = Cf[r * 16 + mm];
                float nc = -cf;
                unsigned long long pc = pk2(nc, nc);
                ulonglong2 g = *(const ulonglong2*)(sG + mm * 68 + c0);
                fma2(aQ0, pc, g.x); fma2(aQ1, pc, g.y);
            }
            float2 yA = up2(aQ0), yB = up2(aQ1);
            float y0 = yA.x, y1 = yA.y, y2 = yB.x, y3 = yB.y;
            float s = hred(y0 + y1 + y2 + y3);
            float qq = hred(y0 * y0 + y1 * y1 + y2 * y2 + y3 * y3);
            float m = s * (1.f / 64.f);
            float rstd = rsqrtf(qq * (1.f / 64.f) - m * m + EPSV);
            float4 o;
            o.x = q4.x + gv0 * ((y0 - m) * rstd) + bv0;
            o.y = q4.y + gv1 * ((y1 - m) * rstd) + bv1;
            o.z = q4.z + gv2 * ((y2 - m) * rstd) + bv2;
            o.w = q4.w + gv3 * ((y3 - m) * rstd) + bv3;
            *(float4*)(g_ttt + offc) = o;
        }

        // W1 -= XK^T @ gvv ; b1 -= sum(gvv). thread = (kb = tid>>6, d = tid&63)
        {
            const int d = tid & 63;
            const int kbase = (tid >> 6) * 16;
            float gvv[16];
            float bs = 0.f;
#pragma unroll
            for (int mm = 0; mm < 16; mm++) {
                gvv[mm] = lrw[mm] * sG[mm * 68 + d];
                bs += gvv[mm];
            }
            unsigned long long acc[8];
#pragma unroll
            for (int j = 0; j < 8; j++) acc[j] = 0ULL;
#pragma unroll
            for (int mm = 0; mm < 16; mm++) {
                unsigned long long gp = pk2(gvv[mm], gvv[mm]);
                ulonglong2 x0 = *(const ulonglong2*)(sXK + mm * 68 + kbase);
                ulonglong2 x1 = *(const ulonglong2*)(sXK + mm * 68 + kbase + 4);
                ulonglong2 x2 = *(const ulonglong2*)(sXK + mm * 68 + kbase + 8);
                ulonglong2 x3 = *(const ulonglong2*)(sXK + mm * 68 + kbase + 12);
                fma2(acc[0], gp, x0.x); fma2(acc[1], gp, x0.y);
                fma2(acc[2], gp, x1.x); fma2(acc[3], gp, x1.y);
                fma2(acc[4], gp, x2.x); fma2(acc[5], gp, x2.y);
                fma2(acc[6], gp, x3.x); fma2(acc[7], gp, x3.y);
            }
#pragma unroll
            for (int j = 0; j < 8; j++) {
                float2 p = up2(acc[j]);
                int k0 = kbase + 2 * j;
                W1s[k0 * 64 + d]       -= p.x;
                W1s[(k0 + 1) * 64 + d] -= p.y;
            }
            if (tid < 64) b1s[tid] -= bs;
        }
    }
}

// ------------------------- post: t = gelu(gate) * LN(out) -> bf16 hi/lo -----
__global__ __launch_bounds__(256) void postfuse_kernel(
    const float* __restrict__ pns, const float* __restrict__ pnb)
{
    __shared__ float ws[8], wq2[8];
    __shared__ float smu, srs;
    const int row = blockIdx.x;
    const int tid = threadIdx.x;
    const int lane = tid & 31, wid = tid >> 5;
    const float* o = g_ttt + (size_t)row * WID;
    const float* gp = g_gate + (size_t)row * WID;

    float v[3], s = 0.f, q = 0.f;
#pragma unroll
    for (int i = 0; i < 3; i++) {
        v[i] = o[tid + i * 256];
        s += v[i]; q += v[i] * v[i];
    }
    s = wred(s); q = wred(q);
    if (lane == 0) { ws[wid] = s; wq2[wid] = q; }
    __syncthreads();
    if (tid == 0) {
        float S = 0.f, Q = 0.f;
#pragma unroll
        for (int i = 0; i < 8; i++) { S += ws[i]; Q += wq2[i]; }
        float m = S * (1.f / 768.f);
        smu = m;
        srs = rsqrtf(Q * (1.f / 768.f) - m * m + EPSV);
    }
    __syncthreads();
    const float m = smu, rs = srs;
#pragma unroll
    for (int i = 0; i < 3; i++) {
        int c = tid + i * 256;
        float z = pns[c] * ((v[i] - m) * rs) + pnb[c];
        float x = gp[c];
        float gl = 0.5f * x * (1.f + tanhf(0.7978845608028654f * (x + 0.044715f * x * x * x)));
        float val = gl * z;
        __nv_bfloat16 hi = __float2bfloat16(val);
        g_th[(size_t)row * WID + c] = hi;
        g_tl[(size_t)row * WID + c] = __float2bfloat16(val - __bfloat162float(hi));
    }
}

// ------------------------- launch --------------------------------------------
extern "C" void kernel_launch(void* const* d_in, const int* in_sizes, int n_in,
                              void* d_out, int out_size)
{
    const float* hidden = (const float*)d_in[0];
    const float* wq  = (const float*)d_in[1];
    const float* wv  = (const float*)d_in[2];
    const float* wo  = (const float*)d_in[3];
    const float* wg  = (const float*)d_in[4];
    const float* cqk = (const float*)d_in[5];
    const float* cqb = (const float*)d_in[6];
    const float* ckk = (const float*)d_in[7];
    const float* ckb = (const float*)d_in[8];
    const float* W1  = (const float*)d_in[9];
    const float* b1  = (const float*)d_in[10];
    const float* tns = (const float*)d_in[11];
    const float* tnb = (const float*)d_in[12];
    const float* lrk = (const float*)d_in[13];
    const float* lrb = (const float*)d_in[14];
    const float* lti = (const float*)d_in[15];
    const float* pns = (const float*)d_in[16];
    const float* pnb = (const float*)d_in[17];
    float* out = (float*)d_out;

    float *p_xqk, *p_xv, *p_gate;
    __nv_bfloat16 *p_hh, *p_hl, *p_th, *p_tl, *p_wt;
    cudaGetSymbolAddress((void**)&p_xqk,  g_xqk);
    cudaGetSymbolAddress((void**)&p_xv,   g_xv);
    cudaGetSymbolAddress((void**)&p_gate, g_gate);
    cudaGetSymbolAddress((void**)&p_hh,   g_hh);
    cudaGetSymbolAddress((void**)&p_hl,   g_hl);
    cudaGetSymbolAddress((void**)&p_th,   g_th);
    cudaGetSymbolAddress((void**)&p_tl,   g_tl);
    cudaGetSymbolAddress((void**)&p_wt,   g_wt);

    const int smem_mma = 2 * STAGEB;   // 81920
    cudaFuncSetAttribute(mma_gemm_kernel, cudaFuncAttributeMaxDynamicSharedMemorySize, smem_mma);

    // 1: lr (only needs hidden)
    lr_kernel<<<MTOT / 8, 256>>>(hidden, lrk, lrb);
    // 2: hidden hi/lo split
    cvt_hilo_kernel<<<(MTOT * WID / 4 + 255) / 256, 256>>>(hidden, p_hh, p_hl, MTOT * WID / 4);
    // 3: all weight transposes+splits
    {
        dim3 tb(32, 8), tg(WID / 32, WID / 32, 4);
        cvt_w_kernel<<<tg, tb>>>(wq, wv, wg, wo);
    }
    // 4: fused QVG GEMM  (profiled launch)
    {
        dim3 gg(18, MTOT / 128);
        mma_gemm_kernel<<<gg, 256, smem_mma>>>(p_hh, p_hl, p_wt, p_wt + (size_t)3 * WW,
                                               p_xqk, p_xv, p_gate);
    }
    // 5: conv + rope
    conv_rope_kernel<<<(Bsz * SEQ * 384 + 255) / 256, 256>>>(cqk, cqb, ckk, ckb);
    // 6: scan
    ttt_scan_kernel<<<Bsz * NH, 256>>>(W1, b1, tns, tnb, lti);
    // 7: post LN * gelu gate
    postfuse_kernel<<<MTOT, 256>>>(pns, pnb);
    // 8: output GEMM
    {
        dim3 gg(6, MTOT / 128);
        mma_gemm_kernel<<<gg, 256, smem_mma>>>(p_th, p_tl, p_wt + (size_t)6 * WW, p_wt + (size_t)7 * WW,
                                               out, out, out);
    }
}